// round 17
// baseline (speedup 1.0000x reference)
#include <cuda_runtime.h>
#include <cuda_bf16.h>
#include <cuda_fp16.h>
#include <cstdint>
#include <math.h>

#define BATCH  4
#define SEQ    4096
#define DMODEL 1024
#define DH     64
#define NCHUNK 8
#define ATTN_BLOCKS 1152    // 4 batches * 288 (sum over qt of qt/8+1)

// ---------------------------------------------------------------------------
// Scratch (device globals, no allocation)
// ---------------------------------------------------------------------------
__device__ float g_qh[BATCH * SEQ * DH];
__device__ float g_kh[BATCH * SEQ * DH];
__device__ float g_vh[BATCH * SEQ * DH];
__device__ float g_po[NCHUNK][BATCH * SEQ * DH];
__device__ float g_pm[NCHUNK][BATCH * SEQ];
__device__ float g_pl[NCHUNK][BATCH * SEQ];
__device__ uint32_t g_wf[3 * 64 * 512];   // W fp16x2 words [which][n][k/2]
// Pre-packed K as fp16 dual-ks quads.
__device__ uint4 g_kp4[BATCH * SEQ * 8];
// Pre-packed V as fp16 dual-kk quads, transposed per 64-key tile.
__device__ uint4 g_vp4[BATCH * SEQ * 8];

// ---------------------------------------------------------------------------
__device__ __forceinline__ void mma16816f16(float c[4], const uint32_t a[4],
                                            uint32_t b0, uint32_t b1) {
    asm volatile(
        "mma.sync.aligned.m16n8k16.row.col.f32.f16.f16.f32 "
        "{%0,%1,%2,%3}, {%4,%5,%6,%7}, {%8,%9}, {%0,%1,%2,%3};"
        : "+f"(c[0]), "+f"(c[1]), "+f"(c[2]), "+f"(c[3])
        : "r"(a[0]), "r"(a[1]), "r"(a[2]), "r"(a[3]), "r"(b0), "r"(b1));
}
__device__ __forceinline__ uint32_t cvt_h2(float a, float b) {
    __half2 h = __floats2half2_rn(a, b);
    return *(uint32_t*)&h;
}

// exp(x/8) via MUFU: single mul + EX2
#define LOG2E_8 0.18033688011112042f
__device__ __forceinline__ float exp8(float x) { return exp2f(x * LOG2E_8); }

// cp.async 16B helpers
__device__ __forceinline__ void cpa16(void* smem, const void* g) {
    uint32_t sa = (uint32_t)__cvta_generic_to_shared(smem);
    asm volatile("cp.async.cg.shared.global [%0], [%1], 16;" :: "r"(sa), "l"(g));
}
#define CPA_COMMIT() asm volatile("cp.async.commit_group;" ::: "memory")
#define CPA_WAIT0()  asm volatile("cp.async.wait_group 0;" ::: "memory")

// ---------------------------------------------------------------------------
__global__ __launch_bounds__(256)
void wconv_kernel(const float* __restrict__ wq, const float* __restrict__ wk,
                  const float* __restrict__ wv)
{
    const int t = blockIdx.x * 256 + threadIdx.x;
    const int which = t >> 15;
    const int p = t & 32767;
    const float* w = (which == 0) ? wq : (which == 1) ? wk : wv;
    float2 f = *(const float2*)(w + 2 * p);
    g_wf[t] = cvt_h2(f.x, f.y);
}

// ---------------------------------------------------------------------------
// Repack K into fp16 dual-ks quads.
// ---------------------------------------------------------------------------
__global__ __launch_bounds__(256)
void kpack_kernel()
{
    const int t = blockIdx.x * 256 + threadIdx.x;   // 0 .. BATCH*SEQ*8-1
    const int row = t >> 3;
    const int e   = t & 7;
    const int tigp = e & 3;
    const int ksp  = e >> 2;
    const int d2a = 8 * ksp + tigp;
    const int d2b = 8 * ksp + 16 + tigp;
    const float* base = g_kh + (size_t)row * DH;
    g_kp4[t] = make_uint4(
        cvt_h2(base[2 * d2a],     base[2 * d2a + 1]),
        cvt_h2(base[2 * d2a + 8], base[2 * d2a + 9]),
        cvt_h2(base[2 * d2b],     base[2 * d2b + 1]),
        cvt_h2(base[2 * d2b + 8], base[2 * d2b + 9]));
}

// ---------------------------------------------------------------------------
// Repack V: per 64-key tile, transpose to [d][k2], fp16 dual-kk quads.
// ---------------------------------------------------------------------------
__global__ __launch_bounds__(256)
void vpack_kernel()
{
    __shared__ float Vt[64 * 65];   // [d][key]
    const int tile = blockIdx.x;
    const int tid = threadIdx.x;
    const float* vt = g_vh + (size_t)tile * 64 * DH;

    #pragma unroll
    for (int it = 0; it < 16; it++) {
        const int idx = it * 256 + tid;
        const int key = idx >> 6;
        const int d   = idx & 63;
        Vt[d * 65 + key] = vt[(size_t)key * DH + d];
    }
    __syncthreads();

    uint4* op = g_vp4 + (size_t)tile * 512;
    #pragma unroll
    for (int it = 0; it < 2; it++) {
        const int idx = it * 256 + tid;     // 0..511 = d*8 + e
        const int d = idx >> 3;
        const int e = idx & 7;
        const int tigp = e & 3;
        const int kkp  = e >> 2;
        const int k2a = 8 * kkp + tigp;
        const int k2b = 8 * kkp + 16 + tigp;
        const float* row = Vt + d * 65;
        op[idx] = make_uint4(
            cvt_h2(row[2 * k2a],      row[2 * k2a + 1]),
            cvt_h2(row[2 * k2a + 8],  row[2 * k2a + 9]),
            cvt_h2(row[2 * k2b],      row[2 * k2b + 1]),
            cvt_h2(row[2 * k2b + 8],  row[2 * k2b + 9]));
    }
}

// ---------------------------------------------------------------------------
// Projection: single-fp16 X and W — 1 MMA per fragment pair (MMA floor /2).
// Block = 64 rows x 64 n, 4 warps, K chunked by 64.
// ---------------------------------------------------------------------------
__global__ __launch_bounds__(128)
void proj_mma_kernel(const float* __restrict__ qin, const float* __restrict__ kin,
                     const float* __restrict__ vin,
                     const float* __restrict__ bq, const float* __restrict__ bk,
                     const float* __restrict__ bv)
{
    __shared__ uint32_t Xs[64 * 36];
    __shared__ uint32_t Wf[64 * 36];

    const int which = blockIdx.y;
    const float* __restrict__ x    = (which == 0) ? qin : (which == 1) ? kin : vin;
    const float* __restrict__ bias = (which == 0) ? bq  : (which == 1) ? bk  : bv;
    float* __restrict__ out        = (which == 0) ? g_qh : (which == 1) ? g_kh : g_vh;
    const uint32_t* __restrict__ wf = g_wf + which * 32768;

    const int tid  = threadIdx.x;
    const int warp = tid >> 5;
    const int lane = tid & 31;
    const int gid  = lane >> 2;
    const int tig  = lane & 3;
    const int row0 = blockIdx.x * 64;

    float acc[8][4] = {};

    for (int kb = 0; kb < 16; kb++) {
        __syncthreads();
        #pragma unroll
        for (int it = 0; it < 8; it++) {
            const int f = it * 128 + tid;
            const int r = f >> 4;
            const int c4 = (f & 15) << 2;
            float4 v = *(const float4*)(x + (size_t)(row0 + r) * DMODEL + kb * 64 + c4);
            *(uint2*)&Xs[r * 36 + (c4 >> 1)] =
                make_uint2(cvt_h2(v.x, v.y), cvt_h2(v.z, v.w));
        }
        #pragma unroll
        for (int it = 0; it < 16; it++) {
            const int f = it * 128 + tid;
            const int n = f >> 5;
            const int k2 = f & 31;
            Wf[n * 36 + k2] = wf[n * 512 + kb * 32 + k2];
        }
        __syncthreads();

        #pragma unroll
        for (int ks = 0; ks < 4; ks++) {
            const int d2 = (ks << 3) + tig;
            const int ra = (warp << 4) + gid;
            uint32_t ah[4];
            ah[0] = Xs[ra * 36 + d2];
            ah[1] = Xs[(ra + 8) * 36 + d2];
            ah[2] = Xs[ra * 36 + d2 + 4];
            ah[3] = Xs[(ra + 8) * 36 + d2 + 4];
            #pragma unroll
            for (int nt = 0; nt < 8; nt++) {
                const int nr = (nt << 3) + gid;
                mma16816f16(acc[nt], ah, Wf[nr * 36 + d2], Wf[nr * 36 + d2 + 4]);
            }
        }
    }

    const int row = row0 + (warp << 4) + gid;
    #pragma unroll
    for (int nt = 0; nt < 8; nt++) {
        const int col = (nt << 3) + (tig << 1);
        const float b0 = bias[col], b1 = bias[col + 1];
        *(float2*)(out + (size_t)row * DH + col) =
            make_float2(acc[nt][0] + b0, acc[nt][1] + b1);
        *(float2*)(out + (size_t)(row + 8) * DH + col) =
            make_float2(acc[nt][2] + b0, acc[nt][3] + b1);
    }
}

// ---------------------------------------------------------------------------
// Flash attention, split-KV, fp16 MMAs, cp.async double-buffered K/V staging.
// ---------------------------------------------------------------------------
__global__ __launch_bounds__(128, 4)
void attn_kernel()
{
    __shared__ uint4 Ksm[2][64 * 12];   // [buf][key][e] (8 used of 12/row)
    __shared__ uint4 Vsm[2][64 * 12];   // [buf][d][e]

    const int tid  = threadIdx.x;
    const int warp = tid >> 5;
    const int lane = tid & 31;
    const int gid  = lane >> 2;
    const int tig  = lane & 3;

    const int bgid = (ATTN_BLOCKS - 1) - blockIdx.x;
    const int bb   = bgid / 288;
    const int r    = bgid - bb * 288;
    int a = 0;
    #pragma unroll
    for (int t = 1; t < 8; t++)
        if (4 * t * (t + 1) <= r) a = t;       // octave: qt in [8a, 8a+8)
    const int rr = r - 4 * a * (a + 1);
    const int qt = 8 * a + rr / (a + 1);
    const int ch = rr - (rr / (a + 1)) * (a + 1);

    const int q0  = qt * 64;
    const int kt0 = ch * 8;
    const int kt1 = min(kt0 + 7, qt);

    const float* __restrict__ qh = g_qh + (size_t)bb * SEQ * DH;
    const uint4* __restrict__ kp4 = g_kp4 + (size_t)bb * SEQ * 8;
    const uint4* __restrict__ vpb = g_vp4 + (size_t)bb * 64 * 512;

    // indices for this thread's staging slice (4 rows x 8-entry halves)
    const int srk = tid >> 3;          // 0..15 -> rows via +16 steps
    const int sc  = tid & 7;           // 0..7

    // prefetch first tile into buf 0
    {
        const int k0 = kt0 * 64;
        const uint4* vp4 = vpb + (size_t)kt0 * 512;
        #pragma unroll
        for (int it = 0; it < 4; it++) {
            const int rk = srk + it * 16;
            cpa16(&Ksm[0][rk * 12 + sc], &kp4[(size_t)(k0 + rk) * 8 + sc]);
            cpa16(&Vsm[0][rk * 12 + sc], &vp4[rk * 8 + sc]);
        }
        CPA_COMMIT();
    }

    // Q fragments as fp16, once (overlaps with the first prefetch)
    uint32_t qf[4][4];
    const int rowA = q0 + (warp << 4) + gid;
    const int rowB = rowA + 8;
    {
        #pragma unroll
        for (int ks = 0; ks < 4; ks++) {
            const float* pA = qh + (size_t)rowA * DH + (ks << 4) + (tig << 1);
            const float* pB = qh + (size_t)rowB * DH + (ks << 4) + (tig << 1);
            float2 f0 = *(const float2*)(pA);
            float2 f1 = *(const float2*)(pB);
            float2 f2 = *(const float2*)(pA + 8);
            float2 f3 = *(const float2*)(pB + 8);
            qf[ks][0] = cvt_h2(f0.x, f0.y);
            qf[ks][1] = cvt_h2(f1.x, f1.y);
            qf[ks][2] = cvt_h2(f2.x, f2.y);
            qf[ks][3] = cvt_h2(f3.x, f3.y);
        }
    }

    float o[8][4] = {};
    float mA = -3.0e38f, mB = -3.0e38f, lA = 0.0f, lB = 0.0f;

    for (int kt = kt0; kt <= kt1; kt++) {
        const int b = (kt - kt0) & 1;
        CPA_WAIT0();
        __syncthreads();   // buf b ready for all; buf b^1 free (last read in kt-2)

        // prefetch next tile into buf b^1 (overlaps compute below)
        if (kt < kt1) {
            const int k0n = (kt + 1) * 64;
            const uint4* vp4 = vpb + (size_t)(kt + 1) * 512;
            #pragma unroll
            for (int it = 0; it < 4; it++) {
                const int rk = srk + it * 16;
                cpa16(&Ksm[b ^ 1][rk * 12 + sc], &kp4[(size_t)(k0n + rk) * 8 + sc]);
                cpa16(&Vsm[b ^ 1][rk * 12 + sc], &vp4[rk * 8 + sc]);
            }
            CPA_COMMIT();
        }

        const int k0 = kt * 64;
        // S = Q K^T (fp16, 32 MMAs)
        float s[8][4] = {};
        #pragma unroll
        for (int nt = 0; nt < 8; nt++) {
            const int krow = ((nt << 3) + gid) * 12;
            uint4 ka = Ksm[b][krow + tig];        // ks=0 (x,y), ks=2 (z,w)
            uint4 kb = Ksm[b][krow + 4 + tig];    // ks=1 (x,y), ks=3 (z,w)
            mma16816f16(s[nt], qf[0], ka.x, ka.y);
            mma16816f16(s[nt], qf[1], kb.x, kb.y);
            mma16816f16(s[nt], qf[2], ka.z, ka.w);
            mma16816f16(s[nt], qf[3], kb.z, kb.w);
        }

        // causal mask on raw scores (diagonal tile only)
        if (kt == qt) {
            #pragma unroll
            for (int nt = 0; nt < 8; nt++) {
                const int cb = k0 + (nt << 3) + (tig << 1);
                if (cb     > rowA) s[nt][0] = -1.0e30f;
                if (cb + 1 > rowA) s[nt][1] = -1.0e30f;
                if (cb     > rowB) s[nt][2] = -1.0e30f;
                if (cb + 1 > rowB) s[nt][3] = -1.0e30f;
            }
        }

        // online softmax on raw scores; exp folds in the 1/8 scale (MUFU)
        float mxA = -3.0e38f, mxB = -3.0e38f;
        #pragma unroll
        for (int nt = 0; nt < 8; nt++) {
            mxA = fmaxf(mxA, fmaxf(s[nt][0], s[nt][1]));
            mxB = fmaxf(mxB, fmaxf(s[nt][2], s[nt][3]));
        }
        mxA = fmaxf(mxA, __shfl_xor_sync(0xffffffffu, mxA, 1));
        mxA = fmaxf(mxA, __shfl_xor_sync(0xffffffffu, mxA, 2));
        mxB = fmaxf(mxB, __shfl_xor_sync(0xffffffffu, mxB, 1));
        mxB = fmaxf(mxB, __shfl_xor_sync(0xffffffffu, mxB, 2));
        const float mnA = fmaxf(mA, mxA), mnB = fmaxf(mB, mxB);
        const float aA = exp8(mA - mnA), aB = exp8(mB - mnB);
        mA = mnA; mB = mnB;
        float sumA = 0.0f, sumB = 0.0f;
        #pragma unroll
        for (int nt = 0; nt < 8; nt++) {
            s[nt][0] = exp8(s[nt][0] - mnA);
            s[nt][1] = exp8(s[nt][1] - mnA);
            s[nt][2] = exp8(s[nt][2] - mnB);
            s[nt][3] = exp8(s[nt][3] - mnB);
            sumA += s[nt][0] + s[nt][1];
            sumB += s[nt][2] + s[nt][3];
        }
        lA = lA * aA + sumA;
        lB = lB * aB + sumB;
        #pragma unroll
        for (int nt = 0; nt < 8; nt++) {
            o[nt][0] *= aA; o[nt][1] *= aA;
            o[nt][2] *= aB; o[nt][3] *= aB;
        }

        // O += P V  (fp16, 32 MMAs)
        uint32_t pf[4][4];
        #pragma unroll
        for (int kk = 0; kk < 4; kk++) {
            pf[kk][0] = cvt_h2(s[2 * kk][0],     s[2 * kk][1]);
            pf[kk][1] = cvt_h2(s[2 * kk][2],     s[2 * kk][3]);
            pf[kk][2] = cvt_h2(s[2 * kk + 1][0], s[2 * kk + 1][1]);
            pf[kk][3] = cvt_h2(s[2 * kk + 1][2], s[2 * kk + 1][3]);
        }
        #pragma unroll
        for (int nt = 0; nt < 8; nt++) {
            const int drow = ((nt << 3) + gid) * 12;
            uint4 va = Vsm[b][drow + tig];        // kk=0 (x,y), kk=2 (z,w)
            uint4 vb = Vsm[b][drow + 4 + tig];    // kk=1 (x,y), kk=3 (z,w)
            mma16816f16(o[nt], pf[0], va.x, va.y);
            mma16816f16(o[nt], pf[1], vb.x, vb.y);
            mma16816f16(o[nt], pf[2], va.z, va.w);
            mma16816f16(o[nt], pf[3], vb.z, vb.w);
        }
    }

    // finalize partials
    lA += __shfl_xor_sync(0xffffffffu, lA, 1);
    lA += __shfl_xor_sync(0xffffffffu, lA, 2);
    lB += __shfl_xor_sync(0xffffffffu, lB, 1);
    lB += __shfl_xor_sync(0xffffffffu, lB, 2);

    const int growA = bb * SEQ + rowA;
    const int growB = bb * SEQ + rowB;
    #pragma unroll
    for (int nt = 0; nt < 8; nt++) {
        const int col = (nt << 3) + (tig << 1);
        *(float2*)&g_po[ch][(size_t)growA * DH + col] = make_float2(o[nt][0], o[nt][1]);
        *(float2*)&g_po[ch][(size_t)growB * DH + col] = make_float2(o[nt][2], o[nt][3]);
    }
    if (tig == 0) {
        g_pm[ch][growA] = mA * 0.125f; g_pl[ch][growA] = lA;
        g_pm[ch][growB] = mB * 0.125f; g_pl[ch][growB] = lB;
    }
}

// ---------------------------------------------------------------------------
__global__ __launch_bounds__(256)
void merge_kernel(float* __restrict__ out)
{
    const int t = blockIdx.x * 256 + threadIdx.x;
    const int row = t >> 4;
    const int cg  = (t & 15) << 2;
    const int q   = row & (SEQ - 1);
    const int nc  = ((q >> 6) >> 3) + 1;     // 512-key chunks

    float mstar = -3.0e38f;
    #pragma unroll 4
    for (int c = 0; c < nc; c++)
        mstar = fmaxf(mstar, g_pm[c][row]);

    float L = 0.0f;
    float4 acc = make_float4(0.f, 0.f, 0.f, 0.f);
    #pragma unroll 4
    for (int c = 0; c < nc; c++) {
        const float wgt = __expf(g_pm[c][row] - mstar);
        L += wgt * g_pl[c][row];
        float4 ov = *(const float4*)&g_po[c][(size_t)row * DH + cg];
        acc.x += wgt * ov.x; acc.y += wgt * ov.y;
        acc.z += wgt * ov.z; acc.w += wgt * ov.w;
    }
    const float inv = 1.0f / L;
    *(float4*)(out + (size_t)row * DH + cg) =
        make_float4(acc.x * inv, acc.y * inv, acc.z * inv, acc.w * inv);
}

// ---------------------------------------------------------------------------
extern "C" void kernel_launch(void* const* d_in, const int* in_sizes, int n_in,
                              void* d_out, int out_size)
{
    (void)in_sizes; (void)n_in; (void)out_size;
    const float* q  = (const float*)d_in[0];
    const float* k  = (const float*)d_in[1];
    const float* v  = (const float*)d_in[2];
    const float* wq = (const float*)d_in[3];
    const float* bq = (const float*)d_in[4];
    const float* wk = (const float*)d_in[5];
    const float* bk = (const float*)d_in[6];
    const float* wv = (const float*)d_in[7];
    const float* bv = (const float*)d_in[8];
    float* out = (float*)d_out;

    static bool configured = false;
    if (!configured) {
        cudaFuncSetAttribute(attn_kernel,
                             cudaFuncAttributePreferredSharedMemoryCarveout, 100);
        configured = true;
    }

    wconv_kernel<<<384, 256>>>(wq, wk, wv);
    dim3 pgrid(BATCH * SEQ / 64, 3);   // (256, 3)
    proj_mma_kernel<<<pgrid, 128>>>(q, k, v, bq, bk, bv);
    kpack_kernel<<<BATCH * SEQ * 8 / 256, 256>>>();
    vpack_kernel<<<BATCH * SEQ / 64, 256>>>();
    attn_kernel<<<ATTN_BLOCKS, 128>>>();
    merge_kernel<<<BATCH * SEQ * 16 / 256, 256>>>(out);
}